// round 1
// baseline (speedup 1.0000x reference)
#include <cuda_runtime.h>
#include <cuda_bf16.h>
#include <mma.h>
#include <math.h>
#include <stdint.h>

using namespace nvcuda;

#define NB 32
#define CH 1024
#define SP 1024
#define CS (1024*1024)

// ---------------- scratch (device globals; no allocation) ----------------
__device__ float g_mu[NB];
__device__ float g_rstd[NB];
__device__ float g_nxsum[NB*CH];
__device__ float g_a[NB*CH];                       // qsum / sqrt(C)
__device__ __nv_bfloat16 g_nxc[(size_t)NB*CS];     // nx, (n, c, s)
__device__ __nv_bfloat16 g_nxj[(size_t)NB*CS];     // nx, (n, s, c)
__device__ __nv_bfloat16 g_kt [(size_t)NB*CS];     // K^T (n, j, c); softmax in-place -> P
__device__ __nv_bfloat16 g_v  [(size_t)NB*CS];     // V   (n, c, i)
__device__ __nv_bfloat16 g_res[(size_t)NB*CS];     // res (n, j, i)
__device__ __nv_bfloat16 g_oT [(size_t)NB*CS];     // out^T (n, j, o)
__device__ __nv_bfloat16 g_wkT[CS];
__device__ __nv_bfloat16 g_wvb[CS];
__device__ __nv_bfloat16 g_woT[CS];

// ---------------- K1: per-sample mean / rstd ----------------
__global__ void k_stats(const float* __restrict__ x) {
    int n = blockIdx.x;
    const float4* xp = (const float4*)(x + (size_t)n * CS);
    double s1 = 0.0, s2 = 0.0;
    for (int i = threadIdx.x; i < CS/4; i += 256) {
        float4 v = xp[i];
        s1 += (double)v.x + (double)v.y + (double)v.z + (double)v.w;
        s2 += (double)v.x*v.x + (double)v.y*v.y + (double)v.z*v.z + (double)v.w*v.w;
    }
    __shared__ double a1[256], a2[256];
    a1[threadIdx.x] = s1; a2[threadIdx.x] = s2;
    __syncthreads();
    for (int st = 128; st > 0; st >>= 1) {
        if (threadIdx.x < st) {
            a1[threadIdx.x] += a1[threadIdx.x + st];
            a2[threadIdx.x] += a2[threadIdx.x + st];
        }
        __syncthreads();
    }
    if (threadIdx.x == 0) {
        double mu  = a1[0] / (double)CS;
        double var = a2[0] / (double)CS - mu * mu;
        g_mu[n]   = (float)mu;
        g_rstd[n] = (float)(1.0 / sqrt(var + 1e-5));
    }
}

// ---------------- K2: weight convert / transpose to bf16 ----------------
__global__ void k_wprep(const float* __restrict__ src, __nv_bfloat16* __restrict__ dst, int trans) {
    __shared__ float t[32][33];
    int r0 = blockIdx.y * 32, c0 = blockIdx.x * 32;
    if (!trans) {
        #pragma unroll
        for (int g = 0; g < 4; g++) {
            int r = r0 + threadIdx.y + g*8;
            dst[(size_t)r*CH + c0 + threadIdx.x] = __float2bfloat16(src[(size_t)r*CH + c0 + threadIdx.x]);
        }
    } else {
        #pragma unroll
        for (int g = 0; g < 4; g++)
            t[threadIdx.y + g*8][threadIdx.x] = src[(size_t)(r0 + threadIdx.y + g*8)*CH + c0 + threadIdx.x];
        __syncthreads();
        #pragma unroll
        for (int g = 0; g < 4; g++)
            dst[(size_t)(c0 + threadIdx.y + g*8)*CH + r0 + threadIdx.x] =
                __float2bfloat16(t[threadIdx.x][threadIdx.y + g*8]);
    }
}

// ---------------- K3: normalize -> nx in both layouts ----------------
__global__ void k_norm(const float* __restrict__ x, const float* __restrict__ lnw,
                       const float* __restrict__ lnb) {
    __shared__ float t[32][33];
    int n = blockIdx.z;
    int c0 = blockIdx.y * 32, s0 = blockIdx.x * 32;
    float mu = g_mu[n], rstd = g_rstd[n];
    size_t base = (size_t)n * CS;
    #pragma unroll
    for (int g = 0; g < 4; g++) {
        int c = c0 + threadIdx.y + g*8;
        int s = s0 + threadIdx.x;
        size_t idx = (size_t)c * SP + s;
        float nx = (x[base + idx] - mu) * rstd * lnw[idx] + lnb[idx];
        g_nxc[base + idx] = __float2bfloat16(nx);
        t[threadIdx.y + g*8][threadIdx.x] = nx;
    }
    __syncthreads();
    #pragma unroll
    for (int g = 0; g < 4; g++) {
        int j = s0 + threadIdx.y + g*8;
        int c = c0 + threadIdx.x;
        g_nxj[base + (size_t)j * CH + c] = __float2bfloat16(t[threadIdx.x][threadIdx.y + g*8]);
    }
}

// ---------------- K4: nxsum[n,c] (exact fp32, from x directly) ----------------
__global__ void k_nxsum(const float* __restrict__ x, const float* __restrict__ lnw,
                        const float* __restrict__ lnb) {
    int r = blockIdx.x * 8 + (threadIdx.x >> 5);
    int lane = threadIdx.x & 31;
    int n = r >> 10, c = r & 1023;
    const float* xr = x   + (size_t)n * CS + (size_t)c * SP;
    const float* wr = lnw + (size_t)c * SP;
    const float* br = lnb + (size_t)c * SP;
    float s1 = 0.f, s2 = 0.f, s3 = 0.f;
    for (int s = lane; s < SP; s += 32) {
        float w = wr[s];
        s1 += xr[s] * w; s2 += w; s3 += br[s];
    }
    #pragma unroll
    for (int off = 16; off; off >>= 1) {
        s1 += __shfl_xor_sync(0xffffffffu, s1, off);
        s2 += __shfl_xor_sync(0xffffffffu, s2, off);
        s3 += __shfl_xor_sync(0xffffffffu, s3, off);
    }
    if (lane == 0) g_nxsum[r] = g_rstd[n] * (s1 - g_mu[n] * s2) + s3;
}

// ---------------- K5: a[n,o] = (wq @ nxsum + S*bq) / sqrt(C) ----------------
__global__ void k_qsum(const float* __restrict__ wq, const float* __restrict__ bq) {
    int r = blockIdx.x * 8 + (threadIdx.x >> 5);
    int lane = threadIdx.x & 31;
    int n = r >> 10, o = r & 1023;
    const float* w  = wq + (size_t)o * CH;
    const float* ns = g_nxsum + (size_t)n * CH;
    float s = 0.f;
    for (int m = lane; m < CH; m += 32) s += w[m] * ns[m];
    #pragma unroll
    for (int off = 16; off; off >>= 1) s += __shfl_xor_sync(0xffffffffu, s, off);
    if (lane == 0) g_a[r] = (s + 1024.0f * bq[o]) * (1.0f / 32.0f);
}

// ---------------- K6: bf16 WMMA GEMM, NN, cp.async double buffered ----------------
__device__ __forceinline__ void cp16(void* s, const void* g) {
    unsigned sa = (unsigned)__cvta_generic_to_shared(s);
    asm volatile("cp.async.cg.shared.global [%0], [%1], 16;\n" :: "r"(sa), "l"(g) : "memory");
}

__device__ __forceinline__ void gemm_load_tile(
    __nv_bfloat16 (*As)[40], __nv_bfloat16 (*Bs)[136],
    const __nv_bfloat16* A, int lda, const __nv_bfloat16* B, int ldb,
    int bm, int bn, int kt, int t)
{
    // A tile: 128 x 32 halves = 512 16B chunks
    {
        int c0 = t, row = c0 >> 2, col = (c0 & 3) << 3;
        cp16(&As[row][col], A + (size_t)(bm + row) * lda + kt * 32 + col);
        int c1 = t + 256; row = c1 >> 2; col = (c1 & 3) << 3;
        cp16(&As[row][col], A + (size_t)(bm + row) * lda + kt * 32 + col);
    }
    // B tile: 32 x 128 halves = 512 16B chunks
    {
        int c0 = t, row = c0 >> 4, col = (c0 & 15) << 3;
        cp16(&Bs[row][col], B + (size_t)(kt * 32 + row) * ldb + bn + col);
        int c1 = t + 256; row = c1 >> 4; col = (c1 & 15) << 3;
        cp16(&Bs[row][col], B + (size_t)(kt * 32 + row) * ldb + bn + col);
    }
}

__global__ __launch_bounds__(256) void k_gemm(
    const __nv_bfloat16* __restrict__ A, long long sA, int lda,
    const __nv_bfloat16* __restrict__ B, long long sB, int ldb,
    __nv_bfloat16* __restrict__ C, long long sC, int ldc,
    int K, const float* __restrict__ bias, int bias_mode)
{
    A += (size_t)blockIdx.z * sA;
    B += (size_t)blockIdx.z * sB;
    C += (size_t)blockIdx.z * sC;
    const int bm = blockIdx.y * 128, bn = blockIdx.x * 128;

    __shared__ __align__(16) __nv_bfloat16 As[2][128][40];
    __shared__ __align__(16) __nv_bfloat16 Bs[2][32][136];
    __shared__ float stage[8][16][16];

    const int t = threadIdx.x;
    const int wid = t >> 5, lane = t & 31;
    const int wm = wid >> 1, wn = wid & 1;   // 4 x 2 warp grid, 32x64 warp tile

    wmma::fragment<wmma::accumulator, 16, 16, 16, float> cf[2][4];
    #pragma unroll
    for (int i = 0; i < 2; i++)
        #pragma unroll
        for (int j = 0; j < 4; j++) wmma::fill_fragment(cf[i][j], 0.0f);

    const int nk = K >> 5;
    gemm_load_tile(As[0], Bs[0], A, lda, B, ldb, bm, bn, 0, t);
    asm volatile("cp.async.commit_group;\n" ::: "memory");

    for (int kt = 0; kt < nk; kt++) {
        int s = kt & 1;
        if (kt + 1 < nk) {
            gemm_load_tile(As[s ^ 1], Bs[s ^ 1], A, lda, B, ldb, bm, bn, kt + 1, t);
            asm volatile("cp.async.commit_group;\n" ::: "memory");
            asm volatile("cp.async.wait_group 1;\n" ::: "memory");
        } else {
            asm volatile("cp.async.wait_group 0;\n" ::: "memory");
        }
        __syncthreads();
        #pragma unroll
        for (int kk = 0; kk < 2; kk++) {
            wmma::fragment<wmma::matrix_a, 16, 16, 16, __nv_bfloat16, wmma::row_major> af[2];
            wmma::fragment<wmma::matrix_b, 16, 16, 16, __nv_bfloat16, wmma::row_major> bf[4];
            #pragma unroll
            for (int i = 0; i < 2; i++)
                wmma::load_matrix_sync(af[i], &As[s][wm * 32 + i * 16][kk * 16], 40);
            #pragma unroll
            for (int j = 0; j < 4; j++)
                wmma::load_matrix_sync(bf[j], &Bs[s][kk * 16][wn * 64 + j * 16], 136);
            #pragma unroll
            for (int i = 0; i < 2; i++)
                #pragma unroll
                for (int j = 0; j < 4; j++)
                    wmma::mma_sync(cf[i][j], af[i], bf[j], cf[i][j]);
        }
        __syncthreads();
    }

    // epilogue: stage each 16x16 frag through smem, add bias, store bf16
    #pragma unroll
    for (int i = 0; i < 2; i++)
        #pragma unroll
        for (int j = 0; j < 4; j++) {
            wmma::store_matrix_sync(&stage[wid][0][0], cf[i][j], 16, wmma::mem_row_major);
            __syncwarp();
            int r0 = bm + wm * 32 + i * 16;
            int c0 = bn + wn * 64 + j * 16;
            #pragma unroll
            for (int e = lane; e < 256; e += 32) {
                int r = e >> 4, c = e & 15;
                float v = stage[wid][r][c];
                if (bias_mode == 1)      v += bias[r0 + r];
                else if (bias_mode == 2) v += bias[c0 + c];
                C[(size_t)(r0 + r) * ldc + c0 + c] = __float2bfloat16(v);
            }
            __syncwarp();
        }
}

// ---------------- K7: softmax over c, in place on g_kt ----------------
__global__ void k_softmax() {
    int n = blockIdx.x >> 10;
    int j = blockIdx.x & 1023;
    __nv_bfloat16* row = g_kt + (size_t)n * CS + (size_t)j * CH;
    const float* a = g_a + (size_t)n * CH;
    int lane = threadIdx.x & 31, wid = threadIdx.x >> 5;
    __shared__ float red[8];

    float l[4];
    float m = -1e30f;
    #pragma unroll
    for (int k = 0; k < 4; k++) {
        int c = threadIdx.x + k * 256;
        l[k] = a[c] * __bfloat162float(row[c]);
        m = fmaxf(m, l[k]);
    }
    #pragma unroll
    for (int off = 16; off; off >>= 1) m = fmaxf(m, __shfl_xor_sync(0xffffffffu, m, off));
    if (lane == 0) red[wid] = m;
    __syncthreads();
    m = red[0];
    #pragma unroll
    for (int i = 1; i < 8; i++) m = fmaxf(m, red[i]);
    __syncthreads();

    float sum = 0.f;
    #pragma unroll
    for (int k = 0; k < 4; k++) { l[k] = expf(l[k] - m); sum += l[k]; }
    #pragma unroll
    for (int off = 16; off; off >>= 1) sum += __shfl_xor_sync(0xffffffffu, sum, off);
    if (lane == 0) red[wid] = sum;
    __syncthreads();
    sum = 0.f;
    #pragma unroll
    for (int i = 0; i < 8; i++) sum += red[i];
    float inv = 1.0f / sum;
    #pragma unroll
    for (int k = 0; k < 4; k++) {
        int c = threadIdx.x + k * 256;
        row[c] = __float2bfloat16(l[k] * inv);
    }
}

// ---------------- K8: final = x + out^T (transposed) + bo ----------------
__global__ void k_final(const float* __restrict__ x, const float* __restrict__ bo,
                        float* __restrict__ out) {
    __shared__ float t[32][33];
    int n = blockIdx.z;
    int o0 = blockIdx.y * 32, j0 = blockIdx.x * 32;
    const __nv_bfloat16* ot = g_oT + (size_t)n * CS;
    #pragma unroll
    for (int g = 0; g < 4; g++) {
        int j = j0 + threadIdx.y + g*8;
        t[threadIdx.y + g*8][threadIdx.x] = __bfloat162float(ot[(size_t)j * CH + o0 + threadIdx.x]);
    }
    __syncthreads();
    #pragma unroll
    for (int g = 0; g < 4; g++) {
        int o = o0 + threadIdx.y + g*8;
        int j = j0 + threadIdx.x;
        size_t idx = (size_t)n * CS + (size_t)o * SP + j;
        out[idx] = x[idx] + bo[o] + t[threadIdx.x][threadIdx.y + g*8];
    }
}

// ---------------- launch ----------------
extern "C" void kernel_launch(void* const* d_in, const int* in_sizes, int n_in,
                              void* d_out, int out_size) {
    const float* x   = (const float*)d_in[0];
    const float* lnw = (const float*)d_in[1];
    const float* lnb = (const float*)d_in[2];
    const float* wq  = (const float*)d_in[3];
    const float* bq  = (const float*)d_in[4];
    const float* wk  = (const float*)d_in[5];
    const float* bk  = (const float*)d_in[6];
    const float* wv  = (const float*)d_in[7];
    const float* bv  = (const float*)d_in[8];
    const float* wo  = (const float*)d_in[9];
    const float* bo  = (const float*)d_in[10];
    float* out = (float*)d_out;

    __nv_bfloat16 *nxc, *nxj, *kt, *v, *res, *oT, *wkT, *wvb, *woT;
    cudaGetSymbolAddress((void**)&nxc, g_nxc);
    cudaGetSymbolAddress((void**)&nxj, g_nxj);
    cudaGetSymbolAddress((void**)&kt,  g_kt);
    cudaGetSymbolAddress((void**)&v,   g_v);
    cudaGetSymbolAddress((void**)&res, g_res);
    cudaGetSymbolAddress((void**)&oT,  g_oT);
    cudaGetSymbolAddress((void**)&wkT, g_wkT);
    cudaGetSymbolAddress((void**)&wvb, g_wvb);
    cudaGetSymbolAddress((void**)&woT, g_woT);

    dim3 tb(32, 8);

    k_stats<<<NB, 256>>>(x);
    k_wprep<<<dim3(32, 32), tb>>>(wk, wkT, 1);
    k_wprep<<<dim3(32, 32), tb>>>(wo, woT, 1);
    k_wprep<<<dim3(32, 32), tb>>>(wv, wvb, 0);
    k_norm <<<dim3(32, 32, NB), tb>>>(x, lnw, lnb);
    k_nxsum<<<NB * CH / 8, 256>>>(x, lnw, lnb);
    k_qsum <<<NB * CH / 8, 256>>>(wq, bq);

    dim3 gg(8, 8, NB);
    // K^T[j,c] = sum_m nxj[j,m] * wkT[m,c] + bk[c]
    k_gemm<<<gg, 256>>>(nxj, CS, CH, wkT, 0, CH, kt, CS, CH, CH, bk, 2);
    // V[c,i]  = sum_m wv[c,m] * nxc[m,i] + bv[c]
    k_gemm<<<gg, 256>>>(wvb, 0, CH, nxc, CS, SP, v, CS, SP, CH, bv, 1);
    // softmax over c (in place: g_kt -> P)
    k_softmax<<<NB * SP, 256>>>();
    // res[j,i] = sum_c P[j,c] * V[c,i]
    k_gemm<<<gg, 256>>>(kt, CS, CH, v, CS, SP, res, CS, SP, CH, nullptr, 0);
    // out^T[j,o] = sum_i res[j,i] * woT[i,o]
    k_gemm<<<gg, 256>>>(res, CS, SP, woT, 0, CH, oT, CS, CH, SP, nullptr, 0);
    // final[n,o,j] = x + out^T transposed + bo
    k_final<<<dim3(32, 32, NB), tb>>>(x, bo, out);
}

// round 3
// speedup vs baseline: 1.9010x; 1.9010x over previous
#include <cuda_runtime.h>
#include <cuda_bf16.h>
#include <math.h>
#include <stdint.h>

#define NB 32
#define CH 1024
#define SP 1024
#define CS (1024*1024)

// ---------------- scratch (device globals; no allocation) ----------------
__device__ float g_mu[NB];
__device__ float g_rstd[NB];
__device__ double g_p1[256], g_p2[256];
__device__ float g_nxsum[NB*CH];
__device__ float g_a[NB*CH];                         // qsum / sqrt(C)
__device__ float g_kvb[2*CH];                        // concat(bk, bv)
__device__ __nv_bfloat16 g_nxj[(size_t)NB*CS];       // nx, (n, s, c) K-major
__device__ __nv_bfloat16 g_kv [(size_t)NB*2*CS];     // row j: [Kt[j,0:1024] | Vt[j,0:1024]]
__device__ __nv_bfloat16 g_res[(size_t)NB*CS];       // res (n, j, i)
__device__ __nv_bfloat16 g_oT [(size_t)NB*CS];       // out^T (n, j, o)
__device__ __nv_bfloat16 g_wkv[2*CS];                // concat(wk, wv) rows, [2048,1024]
__device__ __nv_bfloat16 g_wob[CS];                  // wo as bf16 [o,i]

// ---------------- helpers ----------------
__device__ __forceinline__ void cpasync16(uint32_t saddr, const void* g) {
    asm volatile("cp.async.cg.shared.global [%0], [%1], 16;" :: "r"(saddr), "l"(g) : "memory");
}
__device__ __forceinline__ void ldm_x4(uint32_t* r, uint32_t addr) {
    asm volatile("ldmatrix.sync.aligned.m8n8.x4.shared.b16 {%0,%1,%2,%3}, [%4];"
        : "=r"(r[0]), "=r"(r[1]), "=r"(r[2]), "=r"(r[3]) : "r"(addr));
}
__device__ __forceinline__ void mma_bf16(float* d, const uint32_t* a, const uint32_t* b) {
    asm volatile("mma.sync.aligned.m16n8k16.row.col.f32.bf16.bf16.f32 "
        "{%0,%1,%2,%3}, {%4,%5,%6,%7}, {%8,%9}, {%0,%1,%2,%3};"
        : "+f"(d[0]), "+f"(d[1]), "+f"(d[2]), "+f"(d[3])
        : "r"(a[0]), "r"(a[1]), "r"(a[2]), "r"(a[3]), "r"(b[0]), "r"(b[1]));
}

// ---------------- K1: per-sample mean/rstd, two-phase ----------------
__global__ void k_stats1(const float* __restrict__ x) {
    int n = blockIdx.x >> 3, seg = blockIdx.x & 7;
    const float4* xp = (const float4*)(x + (size_t)n * CS + (size_t)seg * (CS / 8));
    double s1 = 0.0, s2 = 0.0;
    for (int i = threadIdx.x; i < CS / 32; i += 256) {
        float4 v = xp[i];
        s1 += (double)v.x + (double)v.y + (double)v.z + (double)v.w;
        s2 += (double)v.x*v.x + (double)v.y*v.y + (double)v.z*v.z + (double)v.w*v.w;
    }
    __shared__ double a1[256], a2[256];
    a1[threadIdx.x] = s1; a2[threadIdx.x] = s2;
    __syncthreads();
    for (int st = 128; st > 0; st >>= 1) {
        if (threadIdx.x < st) {
            a1[threadIdx.x] += a1[threadIdx.x + st];
            a2[threadIdx.x] += a2[threadIdx.x + st];
        }
        __syncthreads();
    }
    if (threadIdx.x == 0) { g_p1[blockIdx.x] = a1[0]; g_p2[blockIdx.x] = a2[0]; }
}
__global__ void k_stats2() {
    int n = threadIdx.x;
    double s1 = 0.0, s2 = 0.0;
    for (int k = 0; k < 8; k++) { s1 += g_p1[n * 8 + k]; s2 += g_p2[n * 8 + k]; }
    double mu  = s1 / (double)CS;
    double var = s2 / (double)CS - mu * mu;
    g_mu[n]   = (float)mu;
    g_rstd[n] = (float)(1.0 / sqrt(var + 1e-5));
}

// ---------------- K2: weight convert fp32 -> bf16 ----------------
__global__ void k_cvt(const float* __restrict__ s, __nv_bfloat16* __restrict__ d, int n4) {
    int i = blockIdx.x * blockDim.x + threadIdx.x;
    if (i < n4) {
        float4 v = ((const float4*)s)[i];
        __nv_bfloat162 h0 = __floats2bfloat162_rn(v.x, v.y);
        __nv_bfloat162 h1 = __floats2bfloat162_rn(v.z, v.w);
        ((__nv_bfloat162*)d)[i * 2]     = h0;
        ((__nv_bfloat162*)d)[i * 2 + 1] = h1;
    }
}
__global__ void k_bias(const float* __restrict__ bk, const float* __restrict__ bv) {
    int i = blockIdx.x * 256 + threadIdx.x;
    if (i < 1024) g_kvb[i] = bk[i];
    else if (i < 2048) g_kvb[i] = bv[i - 1024];
}

// ---------------- K3: normalize -> nxj (s, c) ----------------
__global__ void k_norm(const float* __restrict__ x, const float* __restrict__ lnw,
                       const float* __restrict__ lnb) {
    __shared__ float tb[32][33];
    int n = blockIdx.z;
    int c0 = blockIdx.y * 32, s0 = blockIdx.x * 32;
    float mu = g_mu[n], rstd = g_rstd[n];
    size_t base = (size_t)n * CS;
    #pragma unroll
    for (int g = 0; g < 4; g++) {
        int c = c0 + threadIdx.y + g*8;
        int s = s0 + threadIdx.x;
        size_t idx = (size_t)c * SP + s;
        tb[threadIdx.y + g*8][threadIdx.x] = (x[base + idx] - mu) * rstd * lnw[idx] + lnb[idx];
    }
    __syncthreads();
    #pragma unroll
    for (int g = 0; g < 4; g++) {
        int j = s0 + threadIdx.y + g*8;
        int c = c0 + threadIdx.x;
        g_nxj[base + (size_t)j * CH + c] = __float2bfloat16(tb[threadIdx.x][threadIdx.y + g*8]);
    }
}

// ---------------- K4: nxsum[n,c] ----------------
__global__ void k_nxsum(const float* __restrict__ x, const float* __restrict__ lnw,
                        const float* __restrict__ lnb) {
    int r = blockIdx.x * 8 + (threadIdx.x >> 5);
    int lane = threadIdx.x & 31;
    int n = r >> 10, c = r & 1023;
    const float* xr = x   + (size_t)n * CS + (size_t)c * SP;
    const float* wr = lnw + (size_t)c * SP;
    const float* br = lnb + (size_t)c * SP;
    float s1 = 0.f, s2 = 0.f, s3 = 0.f;
    for (int s = lane; s < SP; s += 32) {
        float w = wr[s];
        s1 += xr[s] * w; s2 += w; s3 += br[s];
    }
    #pragma unroll
    for (int off = 16; off; off >>= 1) {
        s1 += __shfl_xor_sync(0xffffffffu, s1, off);
        s2 += __shfl_xor_sync(0xffffffffu, s2, off);
        s3 += __shfl_xor_sync(0xffffffffu, s3, off);
    }
    if (lane == 0) g_nxsum[r] = g_rstd[n] * (s1 - g_mu[n] * s2) + s3;
}

// ---------------- K5: a[n,o] = (wq @ nxsum + S*bq) / sqrt(C) ----------------
__global__ void k_qsum(const float* __restrict__ wq, const float* __restrict__ bq) {
    int r = blockIdx.x * 8 + (threadIdx.x >> 5);
    int lane = threadIdx.x & 31;
    int n = r >> 10, o = r & 1023;
    const float* w  = wq + (size_t)o * CH;
    const float* ns = g_nxsum + (size_t)n * CH;
    float s = 0.f;
    for (int m = lane; m < CH; m += 32) s += w[m] * ns[m];
    #pragma unroll
    for (int off = 16; off; off >>= 1) s += __shfl_xor_sync(0xffffffffu, s, off);
    if (lane == 0) g_a[r] = (s + 1024.0f * bq[o]) * (1.0f / 32.0f);
}

// ---------------- K6: mma.sync bf16 GEMM  D[M,N] = A[M,K] * B[N,K]^T (+bias over N) ----
// BM=128, BN=128, BK=64, 3-stage cp.async, 8 warps (2m x 4n), warp tile 64x32.
#define BM 128
#define BN 128
#define BK 64
#define STG 3
#define AS_B (BM*BK*2)
#define BS_B (BN*BK*2)
#define STAGE_B (AS_B + BS_B)
#define SMEM_DYN (STG*STAGE_B)

__global__ __launch_bounds__(256, 1) void k_gemm(
    const __nv_bfloat16* __restrict__ A, long long sA, int lda,
    const __nv_bfloat16* __restrict__ B, long long sB, int ldb,
    __nv_bfloat16* __restrict__ C, long long sC, int ldc,
    int K, const float* __restrict__ bias)
{
    extern __shared__ __align__(16) char dsm[];
    A += (size_t)blockIdx.z * sA;
    B += (size_t)blockIdx.z * sB;
    C += (size_t)blockIdx.z * sC;
    const int bm = blockIdx.y * BM, bn = blockIdx.x * BN;
    const int t = threadIdx.x, l = t & 31, wid = t >> 5;
    const int wm = wid >> 2, wn = wid & 3;      // 2 x 4 warps
    const uint32_t sbase = (uint32_t)__cvta_generic_to_shared(dsm);

    const __nv_bfloat16* Ab = A + (size_t)bm * lda;
    const __nv_bfloat16* Bb = B + (size_t)bn * ldb;

    float acc[4][4][4];
    #pragma unroll
    for (int mi = 0; mi < 4; mi++)
        #pragma unroll
        for (int ni = 0; ni < 4; ni++)
            #pragma unroll
            for (int e = 0; e < 4; e++) acc[mi][ni][e] = 0.f;

    const int nk = K / BK;

    // stage loader: A tile 128x64 + B tile 128x64, SW128 swizzled rows (128B)
    auto load_stage = [&](int s, int i) {
        uint32_t sa = sbase + s * STAGE_B;
        uint32_t sb = sa + AS_B;
        #pragma unroll
        for (int j = 0; j < 4; j++) {
            int idx = t + j * 256;
            int row = idx >> 3, cc = idx & 7;
            uint32_t col = ((uint32_t)(cc * 16)) ^ ((row & 7) << 4);
            cpasync16(sa + row * 128 + col, Ab + (size_t)row * lda + i * BK + cc * 8);
        }
        #pragma unroll
        for (int j = 0; j < 4; j++) {
            int idx = t + j * 256;
            int row = idx >> 3, cc = idx & 7;
            uint32_t col = ((uint32_t)(cc * 16)) ^ ((row & 7) << 4);
            cpasync16(sb + row * 128 + col, Bb + (size_t)row * ldb + i * BK + cc * 8);
        }
    };

    load_stage(0, 0);
    asm volatile("cp.async.commit_group;" ::: "memory");
    load_stage(1, 1);
    asm volatile("cp.async.commit_group;" ::: "memory");

    for (int i = 0; i < nk; i++) {
        if (i + 2 < nk) load_stage((i + 2) % STG, i + 2);
        asm volatile("cp.async.commit_group;" ::: "memory");   // empty group ok at tail
        asm volatile("cp.async.wait_group 2;" ::: "memory");
        __syncthreads();

        uint32_t sa = sbase + (i % STG) * STAGE_B;
        uint32_t sb = sa + AS_B;
        #pragma unroll
        for (int kk = 0; kk < 4; kk++) {
            uint32_t af[4][4], bfr[2][4];
            #pragma unroll
            for (int mi = 0; mi < 4; mi++) {
                int row = wm * 64 + mi * 16 + (l & 15);
                uint32_t col = ((uint32_t)(kk * 32 + ((l >> 4) << 4))) ^ ((row & 7) << 4);
                ldm_x4(af[mi], sa + row * 128 + col);
            }
            #pragma unroll
            for (int p = 0; p < 2; p++) {
                int row = wn * 32 + p * 16 + (l & 7) + ((l & 16) >> 1);
                uint32_t col = ((uint32_t)(kk * 32 + ((l & 8) << 1))) ^ ((row & 7) << 4);
                ldm_x4(bfr[p], sb + row * 128 + col);
            }
            #pragma unroll
            for (int mi = 0; mi < 4; mi++)
                #pragma unroll
                for (int ni = 0; ni < 4; ni++)
                    mma_bf16(acc[mi][ni], af[mi], &bfr[ni >> 1][(ni & 1) * 2]);
        }
        __syncthreads();
    }

    // epilogue: regs -> (bias, bf16) -> smem (reuse stage mem) -> vectorized gmem
    __nv_bfloat16* sbuf = (__nv_bfloat16*)dsm;   // 128 x 136 (pitch 272B)
    #pragma unroll
    for (int mi = 0; mi < 4; mi++)
        #pragma unroll
        for (int ni = 0; ni < 4; ni++) {
            int r0 = wm * 64 + mi * 16 + (l >> 2);
            int c0 = wn * 32 + ni * 8 + 2 * (l & 3);
            float d0 = acc[mi][ni][0], d1 = acc[mi][ni][1];
            float d2 = acc[mi][ni][2], d3 = acc[mi][ni][3];
            if (bias) {
                float b0 = bias[bn + c0], b1 = bias[bn + c0 + 1];
                d0 += b0; d1 += b1; d2 += b0; d3 += b1;
            }
            *(__nv_bfloat162*)&sbuf[r0 * 136 + c0]       = __floats2bfloat162_rn(d0, d1);
            *(__nv_bfloat162*)&sbuf[(r0 + 8) * 136 + c0] = __floats2bfloat162_rn(d2, d3);
        }
    __syncthreads();
    for (int idx = t; idx < (BM * BN) / 8; idx += 256) {
        int row = idx >> 4, cc = idx & 15;
        uint4 v = *(const uint4*)&sbuf[row * 136 + cc * 8];
        *(uint4*)(C + (size_t)(bm + row) * ldc + bn + cc * 8) = v;
    }
}

// ---------------- K7: softmax over c on Kt half of g_kv rows ----------------
__global__ void k_softmax() {
    int n = blockIdx.x >> 10;
    int j = blockIdx.x & 1023;
    __nv_bfloat16* row = g_kv + (size_t)n * 2 * CS + (size_t)j * 2048;
    const float* a = g_a + (size_t)n * CH;
    int lane = threadIdx.x & 31, wid = threadIdx.x >> 5;
    __shared__ float red[8];

    float l[4];
    float m = -1e30f;
    #pragma unroll
    for (int k = 0; k < 4; k++) {
        int c = threadIdx.x + k * 256;
        l[k] = a[c] * __bfloat162float(row[c]);
        m = fmaxf(m, l[k]);
    }
    #pragma unroll
    for (int off = 16; off; off >>= 1) m = fmaxf(m, __shfl_xor_sync(0xffffffffu, m, off));
    if (lane == 0) red[wid] = m;
    __syncthreads();
    m = red[0];
    #pragma unroll
    for (int i = 1; i < 8; i++) m = fmaxf(m, red[i]);
    __syncthreads();

    float sum = 0.f;
    #pragma unroll
    for (int k = 0; k < 4; k++) { l[k] = expf(l[k] - m); sum += l[k]; }
    #pragma unroll
    for (int off = 16; off; off >>= 1) sum += __shfl_xor_sync(0xffffffffu, sum, off);
    if (lane == 0) red[wid] = sum;
    __syncthreads();
    sum = 0.f;
    #pragma unroll
    for (int i = 0; i < 8; i++) sum += red[i];
    float inv = 1.0f / sum;
    #pragma unroll
    for (int k = 0; k < 4; k++) {
        int c = threadIdx.x + k * 256;
        row[c] = __float2bfloat16(l[k] * inv);
    }
}

// ---------------- K8: final = x + out^T (transposed) + bo ----------------
__global__ void k_final(const float* __restrict__ x, const float* __restrict__ bo,
                        float* __restrict__ out) {
    __shared__ float tb[32][33];
    int n = blockIdx.z;
    int o0 = blockIdx.y * 32, j0 = blockIdx.x * 32;
    const __nv_bfloat16* ot = g_oT + (size_t)n * CS;
    #pragma unroll
    for (int g = 0; g < 4; g++) {
        int j = j0 + threadIdx.y + g*8;
        tb[threadIdx.y + g*8][threadIdx.x] = __bfloat162float(ot[(size_t)j * CH + o0 + threadIdx.x]);
    }
    __syncthreads();
    #pragma unroll
    for (int g = 0; g < 4; g++) {
        int o = o0 + threadIdx.y + g*8;
        int j = j0 + threadIdx.x;
        size_t idx = (size_t)n * CS + (size_t)o * SP + j;
        out[idx] = x[idx] + bo[o] + tb[threadIdx.x][threadIdx.y + g*8];
    }
}

// ---------------- launch ----------------
extern "C" void kernel_launch(void* const* d_in, const int* in_sizes, int n_in,
                              void* d_out, int out_size) {
    const float* x   = (const float*)d_in[0];
    const float* lnw = (const float*)d_in[1];
    const float* lnb = (const float*)d_in[2];
    const float* wq  = (const float*)d_in[3];
    const float* bq  = (const float*)d_in[4];
    const float* wk  = (const float*)d_in[5];
    const float* bk  = (const float*)d_in[6];
    const float* wv  = (const float*)d_in[7];
    const float* bv  = (const float*)d_in[8];
    const float* wo  = (const float*)d_in[9];
    const float* bo  = (const float*)d_in[10];
    float* out = (float*)d_out;

    __nv_bfloat16 *nxj, *kv, *res, *oT, *wkv, *wob;
    float *kvb;
    cudaGetSymbolAddress((void**)&nxj, g_nxj);
    cudaGetSymbolAddress((void**)&kv,  g_kv);
    cudaGetSymbolAddress((void**)&res, g_res);
    cudaGetSymbolAddress((void**)&oT,  g_oT);
    cudaGetSymbolAddress((void**)&wkv, g_wkv);
    cudaGetSymbolAddress((void**)&wob, g_wob);
    cudaGetSymbolAddress((void**)&kvb, g_kvb);

    cudaFuncSetAttribute(k_gemm, cudaFuncAttributeMaxDynamicSharedMemorySize, SMEM_DYN);

    dim3 tb32(32, 8);

    k_stats1<<<256, 256>>>(x);
    k_stats2<<<1, 32>>>();
    k_cvt<<<1024, 256>>>(wk, wkv,      CS / 4);
    k_cvt<<<1024, 256>>>(wv, wkv + CS, CS / 4);
    k_cvt<<<1024, 256>>>(wo, wob,      CS / 4);
    k_bias<<<8, 256>>>(bk, bv);
    k_norm <<<dim3(32, 32, NB), tb32>>>(x, lnw, lnb);
    k_nxsum<<<NB * CH / 8, 256>>>(x, lnw, lnb);
    k_qsum <<<NB * CH / 8, 256>>>(wq, bq);

    // fused K/V projection: D[j, 0:2048] = nxj[j,:] @ [wk;wv]^T  (+[bk;bv])
    k_gemm<<<dim3(16, 8, NB), 256, SMEM_DYN>>>(
        nxj, (long long)CS, CH, wkv, 0LL, CH, kv, 2LL*CS, 2*CH, CH, kvb);
    // softmax over channel dim on Kt half (in place -> P)
    k_softmax<<<NB * SP, 256>>>();
    // res[j,i] = sum_c P[j,c] * Vt[i,c]
    k_gemm<<<dim3(8, 8, NB), 256, SMEM_DYN>>>(
        kv, 2LL*CS, 2*CH, kv + CH, 2LL*CS, 2*CH, res, (long long)CS, SP, CH, nullptr);
    // oT[j,o] = sum_i res[j,i] * wo[o,i]
    k_gemm<<<dim3(8, 8, NB), 256, SMEM_DYN>>>(
        res, (long long)CS, SP, wob, 0LL, CH, oT, (long long)CS, CH, SP, nullptr);
    // final[n,o,j] = x + oT^T + bo
    k_final<<<dim3(32, 32, NB), tb32>>>(x, bo, out);
}

// round 4
// speedup vs baseline: 2.0676x; 1.0876x over previous
#include <cuda_runtime.h>
#include <cuda_bf16.h>
#include <math.h>
#include <stdint.h>

#define NB 32
#define CH 1024
#define SP 1024
#define CS (1024*1024)

// ---------------- scratch (device globals; no allocation) ----------------
__device__ float g_mu[NB];
__device__ float g_rstd[NB];
__device__ double g_p1[256], g_p2[256];
__device__ float g_npart[NB*CH*32];                  // per-(n,c,s_tile) partial sums
__device__ float g_nxsum[NB*CH];
__device__ float g_a[NB*CH];                         // qsum / sqrt(C)
__device__ float g_kvb[2*CH];                        // concat(bk, bv)
__device__ __nv_bfloat16 g_nxj[(size_t)NB*CS];       // nx, (n, s, c) K-major
__device__ __nv_bfloat16 g_kv [(size_t)NB*2*CS];     // row j: [Kt | Vt]
__device__ __nv_bfloat16 g_res[(size_t)NB*CS];       // res (n, j, i)
__device__ __nv_bfloat16 g_wkv[2*CS];                // concat(wk, wv), [2048,1024]
__device__ __nv_bfloat16 g_wob[CS];                  // wo as bf16 [o,i]

// ---------------- helpers ----------------
__device__ __forceinline__ void cpasync16(uint32_t saddr, const void* g) {
    asm volatile("cp.async.cg.shared.global [%0], [%1], 16;" :: "r"(saddr), "l"(g) : "memory");
}
__device__ __forceinline__ void ldm_x4(uint32_t* r, uint32_t addr) {
    asm volatile("ldmatrix.sync.aligned.m8n8.x4.shared.b16 {%0,%1,%2,%3}, [%4];"
        : "=r"(r[0]), "=r"(r[1]), "=r"(r[2]), "=r"(r[3]) : "r"(addr));
}
__device__ __forceinline__ void mma_bf16(float* d, const uint32_t* a, const uint32_t* b) {
    asm volatile("mma.sync.aligned.m16n8k16.row.col.f32.bf16.bf16.f32 "
        "{%0,%1,%2,%3}, {%4,%5,%6,%7}, {%8,%9}, {%0,%1,%2,%3};"
        : "+f"(d[0]), "+f"(d[1]), "+f"(d[2]), "+f"(d[3])
        : "r"(a[0]), "r"(a[1]), "r"(a[2]), "r"(a[3]), "r"(b[0]), "r"(b[1]));
}

// ---------------- K1: per-sample mean/rstd, two-phase ----------------
__global__ void k_stats1(const float* __restrict__ x) {
    int n = blockIdx.x >> 3, seg = blockIdx.x & 7;
    const float4* xp = (const float4*)(x + (size_t)n * CS + (size_t)seg * (CS / 8));
    double s1 = 0.0, s2 = 0.0;
    for (int i = threadIdx.x; i < CS / 32; i += 256) {
        float4 v = xp[i];
        s1 += (double)v.x + (double)v.y + (double)v.z + (double)v.w;
        s2 += (double)v.x*v.x + (double)v.y*v.y + (double)v.z*v.z + (double)v.w*v.w;
    }
    __shared__ double a1[256], a2[256];
    a1[threadIdx.x] = s1; a2[threadIdx.x] = s2;
    __syncthreads();
    for (int st = 128; st > 0; st >>= 1) {
        if (threadIdx.x < st) {
            a1[threadIdx.x] += a1[threadIdx.x + st];
            a2[threadIdx.x] += a2[threadIdx.x + st];
        }
        __syncthreads();
    }
    if (threadIdx.x == 0) { g_p1[blockIdx.x] = a1[0]; g_p2[blockIdx.x] = a2[0]; }
}
__global__ void k_stats2() {
    int n = threadIdx.x;
    double s1 = 0.0, s2 = 0.0;
    for (int k = 0; k < 8; k++) { s1 += g_p1[n * 8 + k]; s2 += g_p2[n * 8 + k]; }
    double mu  = s1 / (double)CS;
    double var = s2 / (double)CS - mu * mu;
    g_mu[n]   = (float)mu;
    g_rstd[n] = (float)(1.0 / sqrt(var + 1e-5));
}

// ---------------- K2: weight convert fp32 -> bf16 ----------------
__global__ void k_cvt(const float* __restrict__ s, __nv_bfloat16* __restrict__ d, int n4) {
    int i = blockIdx.x * blockDim.x + threadIdx.x;
    if (i < n4) {
        float4 v = ((const float4*)s)[i];
        ((__nv_bfloat162*)d)[i * 2]     = __floats2bfloat162_rn(v.x, v.y);
        ((__nv_bfloat162*)d)[i * 2 + 1] = __floats2bfloat162_rn(v.z, v.w);
    }
}
__global__ void k_bias(const float* __restrict__ bk, const float* __restrict__ bv) {
    int i = blockIdx.x * 256 + threadIdx.x;
    if (i < 1024) g_kvb[i] = bk[i];
    else if (i < 2048) g_kvb[i] = bv[i - 1024];
}

// ---------------- K3: normalize -> nxj (s, c) + per-tile nxsum partials ----------------
__global__ void k_norm(const float* __restrict__ x, const float* __restrict__ lnw,
                       const float* __restrict__ lnb) {
    __shared__ float tb[32][33];
    int n = blockIdx.z;
    int c0 = blockIdx.y * 32, s0 = blockIdx.x * 32;
    float mu = g_mu[n], rstd = g_rstd[n];
    size_t base = (size_t)n * CS;
    #pragma unroll
    for (int g = 0; g < 4; g++) {
        int c = c0 + threadIdx.y + g*8;
        int s = s0 + threadIdx.x;
        size_t idx = (size_t)c * SP + s;
        float v = (x[base + idx] - mu) * rstd * lnw[idx] + lnb[idx];
        tb[threadIdx.y + g*8][threadIdx.x] = v;
        float ps = v;
        #pragma unroll
        for (int off = 16; off; off >>= 1) ps += __shfl_xor_sync(0xffffffffu, ps, off);
        if (threadIdx.x == 0)
            g_npart[((size_t)n * CH + c) * 32 + blockIdx.x] = ps;
    }
    __syncthreads();
    #pragma unroll
    for (int g = 0; g < 4; g++) {
        int j = s0 + threadIdx.y + g*8;
        int c = c0 + threadIdx.x;
        g_nxj[base + (size_t)j * CH + c] = __float2bfloat16(tb[threadIdx.x][threadIdx.y + g*8]);
    }
}

// ---------------- K4: reduce partials -> nxsum[n,c] ----------------
__global__ void k_nxred() {
    int r = blockIdx.x * 8 + (threadIdx.x >> 5);
    int lane = threadIdx.x & 31;
    float s = g_npart[(size_t)r * 32 + lane];
    #pragma unroll
    for (int off = 16; off; off >>= 1) s += __shfl_xor_sync(0xffffffffu, s, off);
    if (lane == 0) g_nxsum[r] = s;
}

// ---------------- K5: a[n,o] = (wq @ nxsum + S*bq) / sqrt(C) ----------------
__global__ void k_qsum(const float* __restrict__ wq, const float* __restrict__ bq) {
    int r = blockIdx.x * 8 + (threadIdx.x >> 5);
    int lane = threadIdx.x & 31;
    int n = r >> 10, o = r & 1023;
    const float* w  = wq + (size_t)o * CH;
    const float* ns = g_nxsum + (size_t)n * CH;
    float s = 0.f;
    for (int m = lane; m < CH; m += 32) s += w[m] * ns[m];
    #pragma unroll
    for (int off = 16; off; off >>= 1) s += __shfl_xor_sync(0xffffffffu, s, off);
    if (lane == 0) g_a[r] = (s + 1024.0f * bq[o]) * (1.0f / 32.0f);
}

// ---------------- K6: mma.sync bf16 GEMM  D[M,N] = A[M,K] * B[N,K]^T ----------------
// BM=128, BN=256, BK=64, 3-stage cp.async, 8 warps (2m x 4n), warp tile 64x64.
// Epilogues: bf16 C store (+bias over N), or fused final (out = x + D^T + bo, fp32).
#define BM 128
#define BN 256
#define BK 64
#define STG 3
#define AS_B (BM*BK*2)
#define BS_B (BN*BK*2)
#define STAGE_B (AS_B + BS_B)
#define SMEM_DYN (STG*STAGE_B)

__global__ __launch_bounds__(256, 1) void k_gemm(
    const __nv_bfloat16* __restrict__ A, long long sA, int lda,
    const __nv_bfloat16* __restrict__ B, long long sB, int ldb,
    __nv_bfloat16* __restrict__ C, long long sC, int ldc,
    int K, const float* __restrict__ bias,
    const float* __restrict__ xres, const float* __restrict__ bo,
    float* __restrict__ outf)
{
    extern __shared__ __align__(16) char dsm[];
    const int nz = blockIdx.z;
    A += (size_t)nz * sA;
    B += (size_t)nz * sB;
    const int bm = blockIdx.y * BM, bn = blockIdx.x * BN;
    const int t = threadIdx.x, l = t & 31, wid = t >> 5;
    const int wm = wid >> 2, wn = wid & 3;      // 2 x 4 warps, 64x64 each
    const uint32_t sbase = (uint32_t)__cvta_generic_to_shared(dsm);

    const __nv_bfloat16* Ab = A + (size_t)bm * lda;
    const __nv_bfloat16* Bb = B + (size_t)bn * ldb;

    float acc[4][8][4];
    #pragma unroll
    for (int mi = 0; mi < 4; mi++)
        #pragma unroll
        for (int ni = 0; ni < 8; ni++)
            #pragma unroll
            for (int e = 0; e < 4; e++) acc[mi][ni][e] = 0.f;

    const int nk = K / BK;

    auto load_stage = [&](int s, int i) {
        uint32_t sa = sbase + s * STAGE_B;
        uint32_t sb = sa + AS_B;
        #pragma unroll
        for (int j = 0; j < 4; j++) {
            int idx = t + j * 256;
            int row = idx >> 3, cc = idx & 7;
            uint32_t col = ((uint32_t)(cc * 16)) ^ ((row & 7) << 4);
            cpasync16(sa + row * 128 + col, Ab + (size_t)row * lda + i * BK + cc * 8);
        }
        #pragma unroll
        for (int j = 0; j < 8; j++) {
            int idx = t + j * 256;
            int row = idx >> 3, cc = idx & 7;
            uint32_t col = ((uint32_t)(cc * 16)) ^ ((row & 7) << 4);
            cpasync16(sb + row * 128 + col, Bb + (size_t)row * ldb + i * BK + cc * 8);
        }
    };

    load_stage(0, 0);
    asm volatile("cp.async.commit_group;" ::: "memory");
    load_stage(1, 1);
    asm volatile("cp.async.commit_group;" ::: "memory");

    for (int i = 0; i < nk; i++) {
        if (i + 2 < nk) load_stage((i + 2) % STG, i + 2);
        asm volatile("cp.async.commit_group;" ::: "memory");   // empty group ok at tail
        asm volatile("cp.async.wait_group 2;" ::: "memory");
        __syncthreads();

        uint32_t sa = sbase + (i % STG) * STAGE_B;
        uint32_t sb = sa + AS_B;
        #pragma unroll
        for (int kk = 0; kk < 4; kk++) {
            uint32_t af[4][4], bfr[4][4];
            #pragma unroll
            for (int mi = 0; mi < 4; mi++) {
                int row = wm * 64 + mi * 16 + (l & 15);
                uint32_t col = ((uint32_t)(kk * 32 + ((l >> 4) << 4))) ^ ((row & 7) << 4);
                ldm_x4(af[mi], sa + row * 128 + col);
            }
            #pragma unroll
            for (int p = 0; p < 4; p++) {
                int row = wn * 64 + p * 16 + (l & 7) + ((l & 16) >> 1);
                uint32_t col = ((uint32_t)(kk * 32 + ((l & 8) << 1))) ^ ((row & 7) << 4);
                ldm_x4(bfr[p], sb + row * 128 + col);
            }
            #pragma unroll
            for (int mi = 0; mi < 4; mi++)
                #pragma unroll
                for (int ni = 0; ni < 8; ni++)
                    mma_bf16(acc[mi][ni], af[mi], &bfr[ni >> 1][(ni & 1) * 2]);
        }
        __syncthreads();
    }

    if (outf == nullptr) {
        // ---- epilogue A: (optional bias over N) -> bf16 C ----
        __nv_bfloat16* sbuf = (__nv_bfloat16*)dsm;   // 128 x 264
        #pragma unroll
        for (int mi = 0; mi < 4; mi++)
            #pragma unroll
            for (int ni = 0; ni < 8; ni++) {
                int r0 = wm * 64 + mi * 16 + (l >> 2);
                int c0 = wn * 64 + ni * 8 + 2 * (l & 3);
                float d0 = acc[mi][ni][0], d1 = acc[mi][ni][1];
                float d2 = acc[mi][ni][2], d3 = acc[mi][ni][3];
                if (bias) {
                    float b0 = bias[bn + c0], b1 = bias[bn + c0 + 1];
                    d0 += b0; d1 += b1; d2 += b0; d3 += b1;
                }
                *(__nv_bfloat162*)&sbuf[r0 * 264 + c0]       = __floats2bfloat162_rn(d0, d1);
                *(__nv_bfloat162*)&sbuf[(r0 + 8) * 264 + c0] = __floats2bfloat162_rn(d2, d3);
            }
        __syncthreads();
        C += (size_t)nz * sC;
        for (int idx = t; idx < (BM * BN) / 8; idx += 256) {
            int row = idx >> 5, cc = idx & 31;
            uint4 v = *(const uint4*)&sbuf[row * 264 + cc * 8];
            *(uint4*)(C + (size_t)(bm + row) * ldc + bn + cc * 8) = v;
        }
    } else {
        // ---- epilogue B: fused final. out[n,o,j] = x[n,o,j] + bo[o] + D[j,o] ----
        float* st = (float*)dsm;                     // transposed stage: [256 o][132 pitch]
        #pragma unroll
        for (int mi = 0; mi < 4; mi++)
            #pragma unroll
            for (int ni = 0; ni < 8; ni++) {
                int r0 = wm * 64 + mi * 16 + (l >> 2);        // j local
                int c0 = wn * 64 + ni * 8 + 2 * (l & 3);      // o local
                st[c0 * 132 + r0]           = acc[mi][ni][0];
                st[(c0 + 1) * 132 + r0]     = acc[mi][ni][1];
                st[c0 * 132 + r0 + 8]       = acc[mi][ni][2];
                st[(c0 + 1) * 132 + r0 + 8] = acc[mi][ni][3];
            }
        __syncthreads();
        const float* xb = xres + (size_t)nz * CS;
        float* ob = outf + (size_t)nz * CS;
        for (int idx = t; idx < (BM * BN) / 4; idx += 256) {
            int o = idx >> 5, jc = idx & 31;          // 32 float4 chunks per o row
            float4 d = *(const float4*)&st[o * 132 + jc * 4];
            size_t gidx = (size_t)(bn + o) * SP + bm + jc * 4;
            float4 xv = *(const float4*)(xb + gidx);
            float bb = bo[bn + o];
            d.x += xv.x + bb; d.y += xv.y + bb; d.z += xv.z + bb; d.w += xv.w + bb;
            *(float4*)(ob + gidx) = d;
        }
    }
}

// ---------------- K7: softmax over c on Kt half of g_kv rows ----------------
__global__ void k_softmax() {
    int n = blockIdx.x >> 10;
    int j = blockIdx.x & 1023;
    __nv_bfloat16* row = g_kv + (size_t)n * 2 * CS + (size_t)j * 2048;
    const float* a = g_a + (size_t)n * CH;
    int lane = threadIdx.x & 31, wid = threadIdx.x >> 5;
    __shared__ float red[8];

    float l[4];
    float m = -1e30f;
    #pragma unroll
    for (int k = 0; k < 4; k++) {
        int c = threadIdx.x + k * 256;
        l[k] = a[c] * __bfloat162float(row[c]);
        m = fmaxf(m, l[k]);
    }
    #pragma unroll
    for (int off = 16; off; off >>= 1) m = fmaxf(m, __shfl_xor_sync(0xffffffffu, m, off));
    if (lane == 0) red[wid] = m;
    __syncthreads();
    m = red[0];
    #pragma unroll
    for (int i = 1; i < 8; i++) m = fmaxf(m, red[i]);
    __syncthreads();

    float sum = 0.f;
    #pragma unroll
    for (int k = 0; k < 4; k++) { l[k] = expf(l[k] - m); sum += l[k]; }
    #pragma unroll
    for (int off = 16; off; off >>= 1) sum += __shfl_xor_sync(0xffffffffu, sum, off);
    if (lane == 0) red[wid] = sum;
    __syncthreads();
    sum = 0.f;
    #pragma unroll
    for (int i = 0; i < 8; i++) sum += red[i];
    float inv = 1.0f / sum;
    #pragma unroll
    for (int k = 0; k < 4; k++) {
        int c = threadIdx.x + k * 256;
        row[c] = __float2bfloat16(l[k] * inv);
    }
}

// ---------------- launch ----------------
extern "C" void kernel_launch(void* const* d_in, const int* in_sizes, int n_in,
                              void* d_out, int out_size) {
    const float* x   = (const float*)d_in[0];
    const float* lnw = (const float*)d_in[1];
    const float* lnb = (const float*)d_in[2];
    const float* wq  = (const float*)d_in[3];
    const float* bq  = (const float*)d_in[4];
    const float* wk  = (const float*)d_in[5];
    const float* bk  = (const float*)d_in[6];
    const float* wv  = (const float*)d_in[7];
    const float* bv  = (const float*)d_in[8];
    const float* wo  = (const float*)d_in[9];
    const float* bo  = (const float*)d_in[10];
    float* out = (float*)d_out;

    __nv_bfloat16 *nxj, *kv, *res, *wkv, *wob;
    float *kvb;
    cudaGetSymbolAddress((void**)&nxj, g_nxj);
    cudaGetSymbolAddress((void**)&kv,  g_kv);
    cudaGetSymbolAddress((void**)&res, g_res);
    cudaGetSymbolAddress((void**)&wkv, g_wkv);
    cudaGetSymbolAddress((void**)&wob, g_wob);
    cudaGetSymbolAddress((void**)&kvb, g_kvb);

    cudaFuncSetAttribute(k_gemm, cudaFuncAttributeMaxDynamicSharedMemorySize, SMEM_DYN);

    dim3 tb32(32, 8);

    k_stats1<<<256, 256>>>(x);
    k_stats2<<<1, 32>>>();
    k_cvt<<<1024, 256>>>(wk, wkv,      CS / 4);
    k_cvt<<<1024, 256>>>(wv, wkv + CS, CS / 4);
    k_cvt<<<1024, 256>>>(wo, wob,      CS / 4);
    k_bias<<<8, 256>>>(bk, bv);
    k_norm <<<dim3(32, 32, NB), tb32>>>(x, lnw, lnb);
    k_nxred<<<NB * CH / 8, 256>>>();
    k_qsum <<<NB * CH / 8, 256>>>(wq, bq);

    // fused K/V projection: D[j, 0:2048] = nxj[j,:] @ [wk;wv]^T  (+[bk;bv])
    k_gemm<<<dim3(8, 8, NB), 256, SMEM_DYN>>>(
        nxj, (long long)CS, CH, wkv, 0LL, CH, kv, 2LL*CS, 2*CH, CH, kvb,
        nullptr, nullptr, nullptr);
    // softmax over channel dim on Kt half (in place -> P)
    k_softmax<<<NB * SP, 256>>>();
    // res[j,i] = sum_c P[j,c] * Vt[i,c]
    k_gemm<<<dim3(4, 8, NB), 256, SMEM_DYN>>>(
        kv, 2LL*CS, 2*CH, kv + CH, 2LL*CS, 2*CH, res, (long long)CS, SP, CH, nullptr,
        nullptr, nullptr, nullptr);
    // fused out-proj + residual: out[n,o,j] = x + bo[o] + (res @ wo^T)^T
    k_gemm<<<dim3(4, 8, NB), 256, SMEM_DYN>>>(
        res, (long long)CS, SP, wob, 0LL, CH, nullptr, 0LL, 0, SP, nullptr,
        x, bo, out);
}

// round 5
// speedup vs baseline: 2.1038x; 1.0175x over previous
#include <cuda_runtime.h>
#include <cuda_bf16.h>
#include <math.h>
#include <stdint.h>

#define NB 32
#define CH 1024
#define SP 1024
#define CS (1024*1024)

// ---------------- scratch (device globals; no allocation) ----------------
__device__ float g_mu[NB];
__device__ float g_rstd[NB];
__device__ double g_p1[256], g_p2[256];
__device__ float g_npart[NB*CH*32];                  // per-(n,c,s_tile) partial sums
__device__ float g_nxsum[NB*CH];
__device__ float g_a[NB*CH];                         // qsum / sqrt(C)
__device__ float g_kvb[2*CH];                        // concat(bk, bv)
__device__ __nv_bfloat16 g_nxj[(size_t)NB*CS];       // nx, (n, s, c) K-major
__device__ __nv_bfloat16 g_kv [(size_t)NB*2*CS];     // row j: [Kt | Vt]
__device__ __nv_bfloat16 g_res[(size_t)NB*CS];       // res (n, j, i)
__device__ __nv_bfloat16 g_wkv[2*CS];                // concat(wk, wv), [2048,1024]
__device__ __nv_bfloat16 g_wob[CS];                  // wo as bf16 [o,i]

// ---------------- helpers ----------------
__device__ __forceinline__ void cpasync16(uint32_t saddr, const void* g) {
    asm volatile("cp.async.cg.shared.global [%0], [%1], 16;" :: "r"(saddr), "l"(g) : "memory");
}
__device__ __forceinline__ void ldm_x4(uint32_t* r, uint32_t addr) {
    asm volatile("ldmatrix.sync.aligned.m8n8.x4.shared.b16 {%0,%1,%2,%3}, [%4];"
        : "=r"(r[0]), "=r"(r[1]), "=r"(r[2]), "=r"(r[3]) : "r"(addr));
}
__device__ __forceinline__ void mma_bf16(float* d, const uint32_t* a, const uint32_t* b) {
    asm volatile("mma.sync.aligned.m16n8k16.row.col.f32.bf16.bf16.f32 "
        "{%0,%1,%2,%3}, {%4,%5,%6,%7}, {%8,%9}, {%0,%1,%2,%3};"
        : "+f"(d[0]), "+f"(d[1]), "+f"(d[2]), "+f"(d[3])
        : "r"(a[0]), "r"(a[1]), "r"(a[2]), "r"(a[3]), "r"(b[0]), "r"(b[1]));
}

// ---------------- K1: per-sample mean/rstd, two-phase ----------------
__global__ void k_stats1(const float* __restrict__ x) {
    int n = blockIdx.x >> 3, seg = blockIdx.x & 7;
    const float4* xp = (const float4*)(x + (size_t)n * CS + (size_t)seg * (CS / 8));
    double s1 = 0.0, s2 = 0.0;
    for (int i = threadIdx.x; i < CS / 32; i += 256) {
        float4 v = xp[i];
        s1 += (double)v.x + (double)v.y + (double)v.z + (double)v.w;
        s2 += (double)v.x*v.x + (double)v.y*v.y + (double)v.z*v.z + (double)v.w*v.w;
    }
    __shared__ double a1[256], a2[256];
    a1[threadIdx.x] = s1; a2[threadIdx.x] = s2;
    __syncthreads();
    for (int st = 128; st > 0; st >>= 1) {
        if (threadIdx.x < st) {
            a1[threadIdx.x] += a1[threadIdx.x + st];
            a2[threadIdx.x] += a2[threadIdx.x + st];
        }
        __syncthreads();
    }
    if (threadIdx.x == 0) { g_p1[blockIdx.x] = a1[0]; g_p2[blockIdx.x] = a2[0]; }
}
__global__ void k_stats2() {
    int n = threadIdx.x;
    double s1 = 0.0, s2 = 0.0;
    for (int k = 0; k < 8; k++) { s1 += g_p1[n * 8 + k]; s2 += g_p2[n * 8 + k]; }
    double mu  = s1 / (double)CS;
    double var = s2 / (double)CS - mu * mu;
    g_mu[n]   = (float)mu;
    g_rstd[n] = (float)(1.0 / sqrt(var + 1e-5));
}

// ---------------- K2: fused weight prep (wk|wv -> wkv, wo -> wob, bias concat) ----------
__global__ void k_prep(const float* __restrict__ wk, const float* __restrict__ wv,
                       const float* __restrict__ wo,
                       const float* __restrict__ bk, const float* __restrict__ bv) {
    int b = blockIdx.x;
    if (b < 3072) {
        const float* s;
        __nv_bfloat16* d;
        int r = b >> 10;          // 0: wk, 1: wv, 2: wo
        int off = (b & 1023) * 256 + threadIdx.x;
        if (r == 0)      { s = wk; d = (__nv_bfloat16*)g_wkv; }
        else if (r == 1) { s = wv; d = (__nv_bfloat16*)g_wkv + CS; }
        else             { s = wo; d = (__nv_bfloat16*)g_wob; }
        float4 v = ((const float4*)s)[off];
        ((__nv_bfloat162*)d)[off * 2]     = __floats2bfloat162_rn(v.x, v.y);
        ((__nv_bfloat162*)d)[off * 2 + 1] = __floats2bfloat162_rn(v.z, v.w);
    } else {
        int i = (b - 3072) * 256 + threadIdx.x;
        if (i < 1024) g_kvb[i] = bk[i];
        else if (i < 2048) g_kvb[i] = bv[i - 1024];
    }
}

// ---------------- K3: normalize -> nxj (s, c) + per-tile nxsum partials ----------------
__global__ void k_norm(const float* __restrict__ x, const float* __restrict__ lnw,
                       const float* __restrict__ lnb) {
    __shared__ float tb[32][33];
    int n = blockIdx.z;
    int c0 = blockIdx.y * 32, s0 = blockIdx.x * 32;
    float mu = g_mu[n], rstd = g_rstd[n];
    size_t base = (size_t)n * CS;
    #pragma unroll
    for (int g = 0; g < 4; g++) {
        int c = c0 + threadIdx.y + g*8;
        int s = s0 + threadIdx.x;
        size_t idx = (size_t)c * SP + s;
        float v = (x[base + idx] - mu) * rstd * lnw[idx] + lnb[idx];
        tb[threadIdx.y + g*8][threadIdx.x] = v;
        float ps = v;
        #pragma unroll
        for (int off = 16; off; off >>= 1) ps += __shfl_xor_sync(0xffffffffu, ps, off);
        if (threadIdx.x == 0)
            g_npart[((size_t)n * CH + c) * 32 + blockIdx.x] = ps;
    }
    __syncthreads();
    #pragma unroll
    for (int g = 0; g < 4; g++) {
        int j = s0 + threadIdx.y + g*8;
        int c = c0 + threadIdx.x;
        g_nxj[base + (size_t)j * CH + c] = __float2bfloat16(tb[threadIdx.x][threadIdx.y + g*8]);
    }
}

// ---------------- K4: reduce partials -> nxsum[n,c] ----------------
__global__ void k_nxred() {
    int r = blockIdx.x * 8 + (threadIdx.x >> 5);
    int lane = threadIdx.x & 31;
    float s = g_npart[(size_t)r * 32 + lane];
    #pragma unroll
    for (int off = 16; off; off >>= 1) s += __shfl_xor_sync(0xffffffffu, s, off);
    if (lane == 0) g_nxsum[r] = s;
}

// ---------------- K5: a[n,o] = (wq @ nxsum + S*bq) / sqrt(C) ----------------
__global__ void k_qsum(const float* __restrict__ wq, const float* __restrict__ bq) {
    int r = blockIdx.x * 8 + (threadIdx.x >> 5);
    int lane = threadIdx.x & 31;
    int n = r >> 10, o = r & 1023;
    const float* w  = wq + (size_t)o * CH;
    const float* ns = g_nxsum + (size_t)n * CH;
    float s = 0.f;
    for (int m = lane; m < CH; m += 32) s += w[m] * ns[m];
    #pragma unroll
    for (int off = 16; off; off >>= 1) s += __shfl_xor_sync(0xffffffffu, s, off);
    if (lane == 0) g_a[r] = (s + 1024.0f * bq[o]) * (1.0f / 32.0f);
}

// ---------------- K6: mma.sync bf16 GEMM  D[M,N] = A[M,K] * B[N,K]^T ----------------
// BM=128, BN=256, BK=64, 4-stage cp.async (1 sync/iter), 8 warps, warp tile 64x64.
// kk-level fragment double buffering.
#define BM 128
#define BN 256
#define BK 64
#define STG 4
#define AS_B (BM*BK*2)
#define BS_B (BN*BK*2)
#define STAGE_B (AS_B + BS_B)
#define SMEM_DYN (STG*STAGE_B)

__global__ __launch_bounds__(256, 1) void k_gemm(
    const __nv_bfloat16* __restrict__ A, long long sA, int lda,
    const __nv_bfloat16* __restrict__ B, long long sB, int ldb,
    __nv_bfloat16* __restrict__ C, long long sC, int ldc,
    int K, const float* __restrict__ bias,
    const float* __restrict__ xres, const float* __restrict__ bo,
    float* __restrict__ outf)
{
    extern __shared__ __align__(16) char dsm[];
    const int nz = blockIdx.z;
    A += (size_t)nz * sA;
    B += (size_t)nz * sB;
    const int bm = blockIdx.y * BM, bn = blockIdx.x * BN;
    const int t = threadIdx.x, l = t & 31, wid = t >> 5;
    const int wm = wid >> 2, wn = wid & 3;      // 2 x 4 warps, 64x64 each
    const uint32_t sbase = (uint32_t)__cvta_generic_to_shared(dsm);

    const __nv_bfloat16* Ab = A + (size_t)bm * lda;
    const __nv_bfloat16* Bb = B + (size_t)bn * ldb;

    float acc[4][8][4];
    #pragma unroll
    for (int mi = 0; mi < 4; mi++)
        #pragma unroll
        for (int ni = 0; ni < 8; ni++)
            #pragma unroll
            for (int e = 0; e < 4; e++) acc[mi][ni][e] = 0.f;

    const int nk = K / BK;

    auto load_stage = [&](int s, int i) {
        uint32_t sa = sbase + s * STAGE_B;
        uint32_t sb = sa + AS_B;
        #pragma unroll
        for (int j = 0; j < 4; j++) {
            int idx = t + j * 256;
            int row = idx >> 3, cc = idx & 7;
            uint32_t col = ((uint32_t)(cc * 16)) ^ ((row & 7) << 4);
            cpasync16(sa + row * 128 + col, Ab + (size_t)row * lda + i * BK + cc * 8);
        }
        #pragma unroll
        for (int j = 0; j < 8; j++) {
            int idx = t + j * 256;
            int row = idx >> 3, cc = idx & 7;
            uint32_t col = ((uint32_t)(cc * 16)) ^ ((row & 7) << 4);
            cpasync16(sb + row * 128 + col, Bb + (size_t)row * ldb + i * BK + cc * 8);
        }
    };

    // prologue: stages 0..2
    #pragma unroll
    for (int s = 0; s < 3; s++) {
        load_stage(s, s);
        asm volatile("cp.async.commit_group;" ::: "memory");
    }

    // precomputed fragment sub-addresses (kk baked into col term each use)
    const int arow = (l & 15);
    const int brow = (l & 7) + ((l & 16) >> 1);

    uint32_t af[2][4][4], bfr[2][4][4];

    auto load_frags = [&](uint32_t sa, uint32_t sb, int kk, int buf) {
        #pragma unroll
        for (int mi = 0; mi < 4; mi++) {
            int row = wm * 64 + mi * 16 + arow;
            uint32_t col = ((uint32_t)(kk * 32 + ((l >> 4) << 4))) ^ ((row & 7) << 4);
            ldm_x4(af[buf][mi], sa + row * 128 + col);
        }
        #pragma unroll
        for (int p = 0; p < 4; p++) {
            int row = wn * 64 + p * 16 + brow;
            uint32_t col = ((uint32_t)(kk * 32 + ((l & 8) << 1))) ^ ((row & 7) << 4);
            ldm_x4(bfr[buf][p], sb + row * 128 + col);
        }
    };

    for (int i = 0; i < nk; i++) {
        asm volatile("cp.async.wait_group 2;" ::: "memory");
        __syncthreads();
        // issue next stage loads AFTER the sync (slot (i+3)%4 was read in iter i-1)
        if (i + 3 < nk) load_stage((i + 3) & 3, i + 3);
        asm volatile("cp.async.commit_group;" ::: "memory");

        uint32_t sa = sbase + (i & 3) * STAGE_B;
        uint32_t sb = sa + AS_B;
        load_frags(sa, sb, 0, 0);
        #pragma unroll
        for (int kk = 0; kk < 4; kk++) {
            int cur = kk & 1;
            if (kk < 3) load_frags(sa, sb, kk + 1, cur ^ 1);
            #pragma unroll
            for (int mi = 0; mi < 4; mi++)
                #pragma unroll
                for (int ni = 0; ni < 8; ni++)
                    mma_bf16(acc[mi][ni], af[cur][mi], &bfr[cur][ni >> 1][(ni & 1) * 2]);
        }
    }
    __syncthreads();

    if (outf == nullptr) {
        // ---- epilogue A: (optional bias over N) -> bf16 C ----
        __nv_bfloat16* sbuf = (__nv_bfloat16*)dsm;   // 128 x 264
        #pragma unroll
        for (int mi = 0; mi < 4; mi++)
            #pragma unroll
            for (int ni = 0; ni < 8; ni++) {
                int r0 = wm * 64 + mi * 16 + (l >> 2);
                int c0 = wn * 64 + ni * 8 + 2 * (l & 3);
                float d0 = acc[mi][ni][0], d1 = acc[mi][ni][1];
                float d2 = acc[mi][ni][2], d3 = acc[mi][ni][3];
                if (bias) {
                    float b0 = bias[bn + c0], b1 = bias[bn + c0 + 1];
                    d0 += b0; d1 += b1; d2 += b0; d3 += b1;
                }
                *(__nv_bfloat162*)&sbuf[r0 * 264 + c0]       = __floats2bfloat162_rn(d0, d1);
                *(__nv_bfloat162*)&sbuf[(r0 + 8) * 264 + c0] = __floats2bfloat162_rn(d2, d3);
            }
        __syncthreads();
        C += (size_t)nz * sC;
        for (int idx = t; idx < (BM * BN) / 8; idx += 256) {
            int row = idx >> 5, cc = idx & 31;
            uint4 v = *(const uint4*)&sbuf[row * 264 + cc * 8];
            *(uint4*)(C + (size_t)(bm + row) * ldc + bn + cc * 8) = v;
        }
    } else {
        // ---- epilogue B: fused final. out[n,o,j] = x[n,o,j] + bo[o] + D[j,o] ----
        float* st = (float*)dsm;                     // transposed stage: [256 o][132 pitch]
        #pragma unroll
        for (int mi = 0; mi < 4; mi++)
            #pragma unroll
            for (int ni = 0; ni < 8; ni++) {
                int r0 = wm * 64 + mi * 16 + (l >> 2);        // j local
                int c0 = wn * 64 + ni * 8 + 2 * (l & 3);      // o local
                st[c0 * 132 + r0]           = acc[mi][ni][0];
                st[(c0 + 1) * 132 + r0]     = acc[mi][ni][1];
                st[c0 * 132 + r0 + 8]       = acc[mi][ni][2];
                st[(c0 + 1) * 132 + r0 + 8] = acc[mi][ni][3];
            }
        __syncthreads();
        const float* xb = xres + (size_t)nz * CS;
        float* ob = outf + (size_t)nz * CS;
        for (int idx = t; idx < (BM * BN) / 4; idx += 256) {
            int o = idx >> 5, jc = idx & 31;          // 32 float4 chunks per o row
            float4 d = *(const float4*)&st[o * 132 + jc * 4];
            size_t gidx = (size_t)(bn + o) * SP + bm + jc * 4;
            float4 xv = *(const float4*)(xb + gidx);
            float bb = bo[bn + o];
            d.x += xv.x + bb; d.y += xv.y + bb; d.z += xv.z + bb; d.w += xv.w + bb;
            *(float4*)(ob + gidx) = d;
        }
    }
}

// ---------------- K7: softmax over c on Kt half of g_kv rows ----------------
__global__ void k_softmax() {
    int n = blockIdx.x >> 10;
    int j = blockIdx.x & 1023;
    __nv_bfloat16* row = g_kv + (size_t)n * 2 * CS + (size_t)j * 2048;
    const float* a = g_a + (size_t)n * CH;
    int lane = threadIdx.x & 31, wid = threadIdx.x >> 5;
    __shared__ float red[8];

    float l[4];
    float m = -1e30f;
    #pragma unroll
    for (int k = 0; k < 4; k++) {
        int c = threadIdx.x + k * 256;
        l[k] = a[c] * __bfloat162float(row[c]);
        m = fmaxf(m, l[k]);
    }
    #pragma unroll
    for (int off = 16; off; off >>= 1) m = fmaxf(m, __shfl_xor_sync(0xffffffffu, m, off));
    if (lane == 0) red[wid] = m;
    __syncthreads();
    m = red[0];
    #pragma unroll
    for (int i = 1; i < 8; i++) m = fmaxf(m, red[i]);
    __syncthreads();

    float sum = 0.f;
    #pragma unroll
    for (int k = 0; k < 4; k++) { l[k] = expf(l[k] - m); sum += l[k]; }
    #pragma unroll
    for (int off = 16; off; off >>= 1) sum += __shfl_xor_sync(0xffffffffu, sum, off);
    if (lane == 0) red[wid] = sum;
    __syncthreads();
    sum = 0.f;
    #pragma unroll
    for (int i = 0; i < 8; i++) sum += red[i];
    float inv = 1.0f / sum;
    #pragma unroll
    for (int k = 0; k < 4; k++) {
        int c = threadIdx.x + k * 256;
        row[c] = __float2bfloat16(l[k] * inv);
    }
}

// ---------------- launch ----------------
extern "C" void kernel_launch(void* const* d_in, const int* in_sizes, int n_in,
                              void* d_out, int out_size) {
    const float* x   = (const float*)d_in[0];
    const float* lnw = (const float*)d_in[1];
    const float* lnb = (const float*)d_in[2];
    const float* wq  = (const float*)d_in[3];
    const float* bq  = (const float*)d_in[4];
    const float* wk  = (const float*)d_in[5];
    const float* bk  = (const float*)d_in[6];
    const float* wv  = (const float*)d_in[7];
    const float* bv  = (const float*)d_in[8];
    const float* wo  = (const float*)d_in[9];
    const float* bo  = (const float*)d_in[10];
    float* out = (float*)d_out;

    __nv_bfloat16 *nxj, *kv, *res, *wkv, *wob;
    float *kvb;
    cudaGetSymbolAddress((void**)&nxj, g_nxj);
    cudaGetSymbolAddress((void**)&kv,  g_kv);
    cudaGetSymbolAddress((void**)&res, g_res);
    cudaGetSymbolAddress((void**)&wkv, g_wkv);
    cudaGetSymbolAddress((void**)&wob, g_wob);
    cudaGetSymbolAddress((void**)&kvb, g_kvb);

    cudaFuncSetAttribute(k_gemm, cudaFuncAttributeMaxDynamicSharedMemorySize, SMEM_DYN);

    dim3 tb32(32, 8);

    // launch order chosen so the fused-KV GEMM is launch #6 (ncu -s 5 -c 1)
    k_stats1<<<256, 256>>>(x);                              // 1
    k_stats2<<<1, 32>>>();                                  // 2
    k_prep<<<3080, 256>>>(wk, wv, wo, bk, bv);              // 3
    k_norm <<<dim3(32, 32, NB), tb32>>>(x, lnw, lnb);       // 4
    k_nxred<<<NB * CH / 8, 256>>>();                        // 5

    // 6: fused K/V projection: D[j, 0:2048] = nxj[j,:] @ [wk;wv]^T  (+[bk;bv])
    k_gemm<<<dim3(8, 8, NB), 256, SMEM_DYN>>>(
        nxj, (long long)CS, CH, wkv, 0LL, CH, kv, 2LL*CS, 2*CH, CH, kvb,
        nullptr, nullptr, nullptr);

    k_qsum <<<NB * CH / 8, 256>>>(wq, bq);                  // 7 (needs nxred, before softmax)
    k_softmax<<<NB * SP, 256>>>();                          // 8
    // res[j,i] = sum_c P[j,c] * Vt[i,c]
    k_gemm<<<dim3(4, 8, NB), 256, SMEM_DYN>>>(
        kv, 2LL*CS, 2*CH, kv + CH, 2LL*CS, 2*CH, res, (long long)CS, SP, CH, nullptr,
        nullptr, nullptr, nullptr);
    // fused out-proj + residual: out[n,o,j] = x + bo[o] + (res @ wo^T)^T
    k_gemm<<<dim3(4, 8, NB), 256, SMEM_DYN>>>(
        res, (long long)CS, SP, wob, 0LL, CH, nullptr, 0LL, 0, SP, nullptr,
        x, bo, out);
}